// round 10
// baseline (speedup 1.0000x reference)
#include <cuda_runtime.h>

// CTRNN forward on GB300 — round 7: fused kernel, uniform per-step CTA barrier.
// All 4 warps hit one __syncthreads() per scan step (BAR floor ~7cyc, vs the
// ~47cyc named barrier that regressed round 6). Producers (warps 2-3, disjoint
// SMSPs from consumers) compute ONE xp row per step, one batch ahead.
// Inputs (metadata order): x[B,T,D] f32, seq_lengths[B] i32 (forward no-op),
// W_in[H,D] f32, b_in[H] f32, W_hh[H,H] f32, b_hh[H] f32.
// Output: outputs[B,T,H] then h_last[B,H], f32, concatenated flat.

#define BB 256
#define TT 2048
#define DD 32
#define HH 64
#define PF 8                 // steps per batch; TT % PF == 0
#define NB (TT / PF)         // 256 batches

typedef unsigned long long u64;

__device__ __forceinline__ u64 pack2(float lo, float hi) {
    u64 r; asm("mov.b64 %0, {%1, %2};" : "=l"(r) : "f"(lo), "f"(hi)); return r;
}
__device__ __forceinline__ float2 unpack2(u64 v) {
    float2 f; asm("mov.b64 {%0, %1}, %2;" : "=f"(f.x), "=f"(f.y) : "l"(v)); return f;
}
// Packed fp32x2 FMA (Blackwell FFMA2): d = a*b + d.
__device__ __forceinline__ void ffma2(u64& d, u64 a, u64 b) {
    asm("fma.rn.f32x2 %0, %1, %2, %0;" : "+l"(d) : "l"(a), "l"(b));
}
__device__ __forceinline__ u64 add2(u64 a, u64 b) {
    u64 r; asm("add.rn.f32x2 %0, %1, %2;" : "=l"(r) : "l"(a), "l"(b)); return r;
}

#define ALPHA_F ((float)(16.67 / 40.0))
#define OMA_F   ((float)(1.0 - 16.67 / 40.0))

__global__ void __launch_bounds__(128) ctrnn_fused_kernel(
    const float* __restrict__ x,
    const float* __restrict__ W_in,
    const float* __restrict__ b_in,
    const float* __restrict__ W_hh,
    const float* __restrict__ b_hh,
    float* __restrict__ out)
{
    const int b   = blockIdx.x;
    const int tid = threadIdx.x;

    __shared__ __align__(16) float hbuf[2][HH];           // hidden state, dbl-buf
    __shared__ __align__(16) float xpring[2][PF][HH];     // xp batches, dbl-buf
    __shared__ __align__(16) float xstage[2][PF][DD];     // raw x batches, dbl-buf

    const bool is_consumer = (tid < HH);
    const float* xb = x + (size_t)b * TT * DD;

    // ---------------- role-specific register setup ----------------------------
    u64 wk[HH / 2];        // consumer: ALPHA*W_hh row j, k-packed
    u64 wi[DD / 2];        // producer: ALPHA*W_in row pj, k-packed
    float biasj = 0.0f;
    const int j  = tid;          // consumer output index (tid < 64)
    const int pj = tid - HH;     // producer output index (tid >= 64)

    if (is_consumer) {
        #pragma unroll
        for (int k4 = 0; k4 < HH / 4; k4++) {
            float4 v = ((const float4*)(W_hh + j * HH))[k4];
            wk[2 * k4]     = pack2(ALPHA_F * v.x, ALPHA_F * v.y);
            wk[2 * k4 + 1] = pack2(ALPHA_F * v.z, ALPHA_F * v.w);
        }
        hbuf[0][j] = 0.0f;
    } else {
        #pragma unroll
        for (int k4 = 0; k4 < DD / 4; k4++) {
            float4 v = ((const float4*)(W_in + pj * DD))[k4];
            wi[2 * k4]     = pack2(ALPHA_F * v.x, ALPHA_F * v.y);
            wi[2 * k4 + 1] = pack2(ALPHA_F * v.z, ALPHA_F * v.w);
        }
        biasj = ALPHA_F * (b_in[pj] + b_hh[pj]);
    }

    // Producer staging map: 64 producer lanes cover one batch = 8 rows x 8 quads.
    const int sr = pj >> 3;          // staging row  0..7
    const int sq = pj & 7;           // staging quad 0..7

    // ---------------- prologue ------------------------------------------------
    if (!is_consumer) {
        float4 v = ((const float4*)(xb + (size_t)(0 * PF + sr) * DD))[sq];
        ((float4*)xstage[0][sr])[sq] = v;
    }
    __syncthreads();   // S0: xstage[0] visible

    if (!is_consumer) {
        // produce full xp batch 0 -> xpring[0]
        #pragma unroll
        for (int r = 0; r < PF; r++) {
            const ulonglong2* xv = (const ulonglong2*)xstage[0][r];   // broadcast
            u64 a0 = pack2(biasj, 0.0f), a1 = 0;
            #pragma unroll
            for (int i = 0; i < DD / 4; i++) {
                ulonglong2 q = xv[i];
                ffma2(a0, q.x, wi[2 * i]);
                ffma2(a1, q.y, wi[2 * i + 1]);
            }
            float2 s = unpack2(add2(a0, a1));
            xpring[0][r][pj] = s.x + s.y;
        }
        // stage x batch 1 -> xstage[1]
        float4 v = ((const float4*)(xb + (size_t)(1 * PF + sr) * DD))[sq];
        ((float4*)xstage[1][sr])[sq] = v;
    }
    __syncthreads();   // S1: xpring[0] + xstage[1] valid; scan may start

    float hold = 0.0f;
    float xpv  = is_consumer ? xpring[0][0][j] : 0.0f;
    float4 xreg = make_float4(0.f, 0.f, 0.f, 0.f);
    const u64 OMA2 = pack2(OMA_F, 0.0f);
    float* outb = out + (size_t)b * TT * HH;

    // ---------------- main loop: one CTA barrier per scan step ----------------
    for (int n = 0; n < NB; n++) {
        const int rb = n & 1;
        const int cb = rb ^ 1;

        #pragma unroll
        for (int p = 0; p < PF; p++) {
            if (is_consumer) {
                const int t   = n * PF + p;
                const int cur = t & 1;

                // acc = xp(t) + OMA*h_j(t-1) + h(t-1).(ALPHA*W_hh[j,:])
                // OMA*hold folded into an accumulator up front (off the tail).
                u64 a0 = pack2(xpv, 0.0f), a1 = 0, a2 = 0, a3 = 0;
                ffma2(a1, pack2(hold, 0.0f), OMA2);
                const ulonglong2* hv = (const ulonglong2*)hbuf[cur];  // broadcast
                #pragma unroll
                for (int i = 0; i < HH / 4; i++) {    // 16 LDS.128, 32 ffma2
                    ulonglong2 hq = hv[i];
                    if (i & 1) { ffma2(a2, hq.x, wk[2 * i]); ffma2(a3, hq.y, wk[2 * i + 1]); }
                    else       { ffma2(a0, hq.x, wk[2 * i]); ffma2(a1, hq.y, wk[2 * i + 1]); }
                }
                float2 sf = unpack2(add2(add2(a0, a1), add2(a2, a3)));
                float hnew = fmaxf(sf.x + sf.y, 0.0f);

                hbuf[cur ^ 1][j] = hnew;               // STS.32 (on chain)
                outb[(size_t)t * HH + j] = hnew;       // coalesced STG.32
                hold = hnew;

                // Prefetch xp for step t+1 (produced >= 1 batch / 8 barriers ago;
                // cross-batch row 0 was written at step 0 of this batch).
                xpv = (p < PF - 1) ? xpring[rb][p + 1][j]
                                   : xpring[cb][0][j];  // garbage at n==NB-1, unused
            } else {
                // Producer: one xp row (row p of batch n+1) per step.
                if (n + 1 < NB) {
                    const ulonglong2* xv = (const ulonglong2*)xstage[cb][p];
                    u64 a0 = pack2(biasj, 0.0f), a1 = 0;
                    #pragma unroll
                    for (int i = 0; i < DD / 4; i++) {
                        ulonglong2 q = xv[i];
                        ffma2(a0, q.x, wi[2 * i]);
                        ffma2(a1, q.y, wi[2 * i + 1]);
                    }
                    float2 s = unpack2(add2(a0, a1));
                    xpring[cb][p][pj] = s.x + s.y;
                }
                // Stage x batch n+2: LDG at p=0, STS at p=7 (latency hidden).
                if (p == 0 && n + 2 < NB)
                    xreg = ((const float4*)(xb + (size_t)((n + 2) * PF + sr) * DD))[sq];
                if (p == PF - 1 && n + 2 < NB)
                    ((float4*)xstage[rb][sr])[sq] = xreg;
            }

            __syncthreads();   // uniform per-step barrier (BAR.SYNC 0, nw=4)
        }
    }

    if (is_consumer)
        out[(size_t)BB * TT * HH + (size_t)b * HH + j] = hold;
}

extern "C" void kernel_launch(void* const* d_in, const int* in_sizes, int n_in,
                              void* d_out, int out_size) {
    (void)in_sizes; (void)n_in; (void)out_size;
    const float* x    = (const float*)d_in[0];
    // d_in[1] = seq_lengths: forward no-op (mask only gates gradients)
    const float* W_in = (const float*)d_in[2];
    const float* b_in = (const float*)d_in[3];
    const float* W_hh = (const float*)d_in[4];
    const float* b_hh = (const float*)d_in[5];

    ctrnn_fused_kernel<<<BB, 128>>>(x, W_in, b_in, W_hh, b_hh, (float*)d_out);
}